// round 6
// baseline (speedup 1.0000x reference)
#include <cuda_runtime.h>
#include <cuda_bf16.h>
#include <cuda_fp16.h>
#include <math.h>

// Problem constants (match reference)
#define NN 100000
#define EE 1600000
#define F_IN 256
#define F_OUT 64

// Scratch (device globals; no runtime allocation allowed)
__device__ __half g_xh[(size_t)NN * F_OUT];  // projected features (fp16)
__device__ float  g_q[NN];
__device__ float  g_k[NN];
__device__ float  g_w[EE];                   // unnormalized edge weights
__device__ int    g_rp[NN + 1];

// ---------------------------------------------------------------------------
// tf32 helpers
// ---------------------------------------------------------------------------
__device__ __forceinline__ unsigned tf32u(float x) {
    unsigned u;
    asm("cvt.rna.tf32.f32 %0, %1;" : "=r"(u) : "f"(x));
    return u;
}
__device__ __forceinline__ void mma_tf32(float* d,
    unsigned a0, unsigned a1, unsigned a2, unsigned a3,
    unsigned b0, unsigned b1)
{
    asm("mma.sync.aligned.m16n8k8.row.col.f32.tf32.tf32.f32 "
        "{%0,%1,%2,%3},{%4,%5,%6,%7},{%8,%9},{%0,%1,%2,%3};"
        : "+f"(d[0]), "+f"(d[1]), "+f"(d[2]), "+f"(d[3])
        : "r"(a0), "r"(a1), "r"(a2), "r"(a3), "r"(b0), "r"(b1));
}

// ---------------------------------------------------------------------------
// Kernel 1: x = nf @ Wv via tf32 tensor cores, single-rounded A and B.
// BM=128, BK=32, 256 threads = 8 warps; warp w owns one m16 tile
// (rows [16w, 16w+16)) -> 32 accumulator regs/thread, better occupancy.
// Epilogue: x written as fp16; q/k fused via shfl reduction over fc lanes.
// ---------------------------------------------------------------------------
#define A_STRIDE 36   // words per A row in smem (conflict-free frag loads)
#define B_STRIDE 72   // words per B row in smem

__global__ __launch_bounds__(256) void gemm_tc_kernel(
    const float* __restrict__ nf, const float* __restrict__ Wv,
    const float* __restrict__ wq, const float* __restrict__ wk,
    __half* __restrict__ xh, float* __restrict__ qo, float* __restrict__ ko,
    int n)
{
    __shared__ __align__(16) unsigned As[128 * A_STRIDE];  // tf32 A 128x32
    __shared__ __align__(16) unsigned Bs[32 * B_STRIDE];   // tf32 B 32x64
    __shared__ float sWq[64], sWk[64];

    const int t    = threadIdx.x;
    const int lane = t & 31;
    const int w    = t >> 5;           // warp 0..7
    const int m0   = blockIdx.x * 128;

    if (t < 64) { sWq[t] = wq[t]; sWk[t] = wk[t]; }

    // load mappings
    const int aq = t & 7;          // A col-quad 0..7
    const int ar = t >> 3;         // A base row 0..31 (+32*i)
    const int bq = t & 15;         // B col-quad 0..15
    const int bk = t >> 4;         // B base k 0..15 (+16*i)

    float4 pa[4];
    float4 pb[2];

    // prefetch tile 0
#pragma unroll
    for (int i = 0; i < 4; ++i) {
        int gm = m0 + ar + 32 * i;
        pa[i] = (gm < n)
            ? *reinterpret_cast<const float4*>(&nf[(size_t)gm * F_IN + aq * 4])
            : make_float4(0.f, 0.f, 0.f, 0.f);
    }
#pragma unroll
    for (int i = 0; i < 2; ++i)
        pb[i] = *reinterpret_cast<const float4*>(
            &Wv[(size_t)(bk + 16 * i) * F_OUT + bq * 4]);

    float d[8][4];
#pragma unroll
    for (int nt = 0; nt < 8; ++nt)
#pragma unroll
        for (int c = 0; c < 4; ++c) d[nt][c] = 0.f;

    const int fr = lane >> 2;   // fragment row 0..7
    const int fc = lane & 3;    // fragment col 0..3

    for (int kt = 0; kt < F_IN / 32; ++kt) {
        // stage prefetched tile into smem, converting to tf32
#pragma unroll
        for (int i = 0; i < 4; ++i) {
            uint4 u = make_uint4(tf32u(pa[i].x), tf32u(pa[i].y),
                                 tf32u(pa[i].z), tf32u(pa[i].w));
            *reinterpret_cast<uint4*>(&As[(ar + 32 * i) * A_STRIDE + aq * 4]) = u;
        }
#pragma unroll
        for (int i = 0; i < 2; ++i) {
            uint4 u = make_uint4(tf32u(pb[i].x), tf32u(pb[i].y),
                                 tf32u(pb[i].z), tf32u(pb[i].w));
            *reinterpret_cast<uint4*>(&Bs[(bk + 16 * i) * B_STRIDE + bq * 4]) = u;
        }
        __syncthreads();

        // prefetch next tile (overlaps with mma below)
        if (kt + 1 < F_IN / 32) {
            int k0n = (kt + 1) * 32;
#pragma unroll
            for (int i = 0; i < 4; ++i) {
                int gm = m0 + ar + 32 * i;
                pa[i] = (gm < n)
                    ? *reinterpret_cast<const float4*>(
                          &nf[(size_t)gm * F_IN + k0n + aq * 4])
                    : make_float4(0.f, 0.f, 0.f, 0.f);
            }
#pragma unroll
            for (int i = 0; i < 2; ++i)
                pb[i] = *reinterpret_cast<const float4*>(
                    &Wv[(size_t)(k0n + bk + 16 * i) * F_OUT + bq * 4]);
        }

        // mma over the smem tile: pure LDS + MMA
#pragma unroll
        for (int kk = 0; kk < 32; kk += 8) {
            int r = w * 16 + fr;
            unsigned a0 = As[r * A_STRIDE + kk + fc];
            unsigned a1 = As[(r + 8) * A_STRIDE + kk + fc];
            unsigned a2 = As[r * A_STRIDE + kk + fc + 4];
            unsigned a3 = As[(r + 8) * A_STRIDE + kk + fc + 4];
#pragma unroll
            for (int nt = 0; nt < 8; ++nt) {
                unsigned b0 = Bs[(kk + fc) * B_STRIDE + nt * 8 + fr];
                unsigned b1 = Bs[(kk + 4 + fc) * B_STRIDE + nt * 8 + fr];
                mma_tf32(d[nt], a0, a1, a2, a3, b0, b1);
            }
        }
        __syncthreads();
    }

    // epilogue: write x (fp16) and fused q/k
#pragma unroll
    for (int nt = 0; nt < 8; ++nt) {
        int col = nt * 8 + 2 * fc;
        int r0 = m0 + w * 16 + fr;
        int r1 = r0 + 8;
        if (r0 < n)
            *reinterpret_cast<half2*>(&xh[(size_t)r0 * F_OUT + col]) =
                __floats2half2_rn(d[nt][0], d[nt][1]);
        if (r1 < n)
            *reinterpret_cast<half2*>(&xh[(size_t)r1 * F_OUT + col]) =
                __floats2half2_rn(d[nt][2], d[nt][3]);
    }
#pragma unroll
    for (int half = 0; half < 2; ++half) {
        float qp = 0.f, kp = 0.f;
#pragma unroll
        for (int nt = 0; nt < 8; ++nt) {
            int col = nt * 8 + 2 * fc;
            float v0 = d[nt][half * 2 + 0];
            float v1 = d[nt][half * 2 + 1];
            qp += v0 * sWq[col] + v1 * sWq[col + 1];
            kp += v0 * sWk[col] + v1 * sWk[col + 1];
        }
        qp += __shfl_xor_sync(0xFFFFFFFFu, qp, 1);
        qp += __shfl_xor_sync(0xFFFFFFFFu, qp, 2);
        kp += __shfl_xor_sync(0xFFFFFFFFu, kp, 1);
        kp += __shfl_xor_sync(0xFFFFFFFFu, kp, 2);
        int r = m0 + w * 16 + half * 8 + fr;
        if (fc == 0 && r < n) { qo[r] = qp; ko[r] = kp; }
    }
}

// ---------------------------------------------------------------------------
// Kernel 2: row_ptr by binary search (row is sorted)
// ---------------------------------------------------------------------------
__global__ void rowptr_kernel(const int* __restrict__ row, int* __restrict__ rp,
                              int n, int e)
{
    int i = blockIdx.x * blockDim.x + threadIdx.x;
    if (i > n) return;
    int lo = 0, hi = e;
    while (lo < hi) {
        int mid = (lo + hi) >> 1;
        if (row[mid] < i) lo = mid + 1; else hi = mid;
    }
    rp[i] = lo;
}

// ---------------------------------------------------------------------------
// Kernel 3: edge-parallel unnormalized weights
//   w[e] = exp(leaky_relu(kk[col[e]] + q[row[e]]))
// Pure coalesced row/col reads + small q/kk gathers (arrays fit in L1/L2).
// ---------------------------------------------------------------------------
__global__ __launch_bounds__(256) void edgew_kernel(
    const int* __restrict__ row, const int* __restrict__ col,
    const float* __restrict__ q, const float* __restrict__ kk,
    float* __restrict__ wbuf, int e)
{
    int t = blockIdx.x * blockDim.x + threadIdx.x;
    if (t >= e) return;
    float l = kk[col[t]] + q[row[t]];
    l = (l > 0.f) ? l : 0.2f * l;
    wbuf[t] = __expf(l);
}

// ---------------------------------------------------------------------------
// Kernel 4: weighted aggregation (warp per node).
//   out[i] = (sum_e w[e] * x[col[e]]) / (sum_e w[e]) + b
// 4 edges/step x 8 lanes x 16B fp16 gather. w/col read DIRECTLY per group
// (no shfl chain) -> independent loads every iteration -> high MLP.
// ---------------------------------------------------------------------------
__global__ __launch_bounds__(256) void gat_kernel(
    const int* __restrict__ rp, const int* __restrict__ col,
    const float* __restrict__ wbuf, const __half* __restrict__ xh,
    const float* __restrict__ b, float* __restrict__ out, int n)
{
    int i    = (blockIdx.x * blockDim.x + threadIdx.x) >> 5;
    int lane = threadIdx.x & 31;
    if (i >= n) return;

    const int eighth = lane >> 3;  // 0..3: edge slot within quad
    const int fl     = lane & 7;   // 16B chunk 0..7 -> features fl*8..fl*8+7

    float4 b0 = reinterpret_cast<const float4*>(b)[fl * 2];
    float4 b1 = reinterpret_cast<const float4*>(b)[fl * 2 + 1];
    float* orow = &out[(size_t)i * F_OUT];

    int s = rp[i], e = rp[i + 1];
    if (e == s) {               // empty segment: out = b
        if (eighth == 0) {
            *reinterpret_cast<float4*>(&orow[fl * 8])     = b0;
            *reinterpret_cast<float4*>(&orow[fl * 8 + 4]) = b1;
        }
        return;
    }

    float acc[8];
#pragma unroll
    for (int z = 0; z < 8; ++z) acc[z] = 0.f;
    float ssum = 0.f;

#pragma unroll 4
    for (int base = s; base < e; base += 4) {
        int tt = base + eighth;
        bool v = (tt < e);
        float w = 0.f;
        int   c = 0;
        if (v) { w = wbuf[tt]; c = col[tt]; }
        if (fl == 0) ssum += w;
        if (v) {
            const uint4 hv = *reinterpret_cast<const uint4*>(
                &xh[(size_t)c * F_OUT + fl * 8]);
            float2 f0 = __half22float2(*reinterpret_cast<const half2*>(&hv.x));
            float2 f1 = __half22float2(*reinterpret_cast<const half2*>(&hv.y));
            float2 f2 = __half22float2(*reinterpret_cast<const half2*>(&hv.z));
            float2 f3 = __half22float2(*reinterpret_cast<const half2*>(&hv.w));
            acc[0] = fmaf(w, f0.x, acc[0]);
            acc[1] = fmaf(w, f0.y, acc[1]);
            acc[2] = fmaf(w, f1.x, acc[2]);
            acc[3] = fmaf(w, f1.y, acc[3]);
            acc[4] = fmaf(w, f2.x, acc[4]);
            acc[5] = fmaf(w, f2.y, acc[5]);
            acc[6] = fmaf(w, f3.x, acc[6]);
            acc[7] = fmaf(w, f3.y, acc[7]);
        }
    }

    // total weight across warp (only fl==0 lanes contributed)
#pragma unroll
    for (int o = 16; o; o >>= 1) ssum += __shfl_xor_sync(0xFFFFFFFFu, ssum, o);
    float inv = 1.0f / ssum;

    // combine the four quad accumulators (same features, different edges)
#pragma unroll
    for (int z = 0; z < 8; ++z) {
        acc[z] += __shfl_xor_sync(0xFFFFFFFFu, acc[z], 8);
        acc[z] += __shfl_xor_sync(0xFFFFFFFFu, acc[z], 16);
    }

    if (eighth == 0) {
        float4 r0, r1;
        r0.x = fmaf(acc[0], inv, b0.x);
        r0.y = fmaf(acc[1], inv, b0.y);
        r0.z = fmaf(acc[2], inv, b0.z);
        r0.w = fmaf(acc[3], inv, b0.w);
        r1.x = fmaf(acc[4], inv, b1.x);
        r1.y = fmaf(acc[5], inv, b1.y);
        r1.z = fmaf(acc[6], inv, b1.z);
        r1.w = fmaf(acc[7], inv, b1.w);
        *reinterpret_cast<float4*>(&orow[fl * 8])     = r0;
        *reinterpret_cast<float4*>(&orow[fl * 8 + 4]) = r1;
    }
}

// ---------------------------------------------------------------------------
extern "C" void kernel_launch(void* const* d_in, const int* in_sizes, int n_in,
                              void* d_out, int out_size)
{
    const float* nf  = (const float*)d_in[0];   // [N, 256]
    const int*   row = (const int*)d_in[1];     // [E]
    const int*   col = (const int*)d_in[2];     // [E]
    const float* Wv  = (const float*)d_in[3];   // [256, 64]
    const float* wq  = (const float*)d_in[4];   // [64]
    const float* wk  = (const float*)d_in[5];   // [64]
    const float* b   = (const float*)d_in[6];   // [64]
    float* out = (float*)d_out;                  // [N, 64]

    const int n = NN;
    const int e = EE;

    __half* xhbuf;
    float *qbuf, *kbuf, *wbuf;
    int *rpbuf;
    cudaGetSymbolAddress((void**)&xhbuf, g_xh);
    cudaGetSymbolAddress((void**)&qbuf, g_q);
    cudaGetSymbolAddress((void**)&kbuf, g_k);
    cudaGetSymbolAddress((void**)&wbuf, g_w);
    cudaGetSymbolAddress((void**)&rpbuf, g_rp);

    // 1) projection GEMM (tf32) + fused q/k epilogue, fp16 x out
    gemm_tc_kernel<<<(n + 127) / 128, 256>>>(nf, Wv, wq, wk, xhbuf, qbuf, kbuf, n);
    // 2) CSR offsets (independent of GEMM)
    rowptr_kernel<<<(n + 1 + 255) / 256, 256>>>(row, rpbuf, n, e);
    // 3) edge weights (needs q/k from GEMM)
    edgew_kernel<<<(e + 255) / 256, 256>>>(row, col, qbuf, kbuf, wbuf, e);
    // 4) weighted aggregation (warp per node)
    gat_kernel<<<(n + 7) / 8, 256>>>(rpbuf, col, wbuf, xhbuf, b, out, n);
}